// round 16
// baseline (speedup 1.0000x reference)
#include <cuda_runtime.h>
#include <cuda_bf16.h>
#include <math.h>
#include <stdint.h>

#define NROWS 128
#define VOCAB 50257
#define HDIM  4096
#define LTOK  200

// ==================== A pre-split (fp32 -> bf16 hi + bf16 lo) ====================

__device__ __nv_bfloat16 g_Ah[NROWS * HDIM];
__device__ __nv_bfloat16 g_Al[NROWS * HDIM];

__global__ void convert_a_kernel(const float* __restrict__ A) {
    int i = (blockIdx.x * blockDim.x + threadIdx.x) * 4;
    if (i >= NROWS * HDIM) return;
    float4 a = *(const float4*)(A + i);
    __nv_bfloat162 h01 = __floats2bfloat162_rn(a.x, a.y);
    __nv_bfloat162 h23 = __floats2bfloat162_rn(a.z, a.w);
    float r0 = a.x - __bfloat162float(h01.x);
    float r1 = a.y - __bfloat162float(h01.y);
    float r2 = a.z - __bfloat162float(h23.x);
    float r3 = a.w - __bfloat162float(h23.y);
    __nv_bfloat162 l01 = __floats2bfloat162_rn(r0, r1);
    __nv_bfloat162 l23 = __floats2bfloat162_rn(r2, r3);
    *(uint2*)(g_Ah + i) = make_uint2(*(uint32_t*)&h01, *(uint32_t*)&h23);
    *(uint2*)(g_Al + i) = make_uint2(*(uint32_t*)&l01, *(uint32_t*)&l23);
}

// ==================== HMMA GEMM: C[128,V] = A[128,H] * B[V,H]^T ====================
// KC=128 variant: 32 chunks (half the barriers of the proven KC=64 config),
// M128xN64 CTA, 256 threads, 1 CTA/SM (204KB smem), 3 split-bf16 terms.

#define KC 128
#define NCHUNK (HDIM / KC)            // 32
#define SPITCH 136                    // bf16 per smem row (128 + 8 pad); 272B, 17x16B
#define A_BYTES (128 * SPITCH * 2)    // 34816 per array
#define B_BYTES (64 * SPITCH * 2)     // 17408 per array
#define STAGE_BYTES (2 * A_BYTES + 2 * B_BYTES)  // 104448
#define GEMM_T 256
#define NTILE 64
#define SMEM_DYN (2 * STAGE_BYTES)    // 208896

__device__ __forceinline__ uint32_t smem_u32(const void* p) {
    uint32_t a;
    asm("{ .reg .u64 t; cvta.to.shared.u64 t, %1; cvt.u32.u64 %0, t; }" : "=r"(a) : "l"(p));
    return a;
}
__device__ __forceinline__ void ldsm_x4(uint32_t* r, uint32_t addr) {
    asm volatile("ldmatrix.sync.aligned.m8n8.x4.shared.b16 {%0,%1,%2,%3}, [%4];"
                 : "=r"(r[0]), "=r"(r[1]), "=r"(r[2]), "=r"(r[3]) : "r"(addr));
}
__device__ __forceinline__ void mma_bf16(float* d, const uint32_t* a, uint32_t b0, uint32_t b1) {
    asm volatile("mma.sync.aligned.m16n8k16.row.col.f32.bf16.bf16.f32 "
                 "{%0,%1,%2,%3}, {%4,%5,%6,%7}, {%8,%9}, {%0,%1,%2,%3};"
                 : "+f"(d[0]), "+f"(d[1]), "+f"(d[2]), "+f"(d[3])
                 : "r"(a[0]), "r"(a[1]), "r"(a[2]), "r"(a[3]), "r"(b0), "r"(b1));
}
__device__ __forceinline__ void cp16(uint32_t dst, const void* src) {
    asm volatile("cp.async.cg.shared.global [%0], [%1], 16;" :: "r"(dst), "l"(src) : "memory");
}

extern __shared__ char dynsmem[];

__global__ __launch_bounds__(GEMM_T, 1) void gemm_hmma(
    const float* __restrict__ B, float* __restrict__ C)
{
    char* sm = dynsmem;
    const uint32_t sbase = smem_u32(sm);
    const int tid = threadIdx.x;
    const int l   = tid & 31;
    const int w   = tid >> 5;         // 0..7
    const int wm  = w & 3;            // 4 M blocks of 32
    const int wn  = w >> 2;           // 2 N blocks of 32
    const int v0  = blockIdx.x * NTILE;

    const int a_off = (l & 15) * SPITCH + ((l >> 4) << 3);
    const int b_off = (((l >> 4) << 3) + (l & 7)) * SPITCH + (((l >> 3) & 1) << 3);

    float acc[2][4][4];
#pragma unroll
    for (int mt = 0; mt < 2; mt++)
#pragma unroll
        for (int nt = 0; nt < 4; nt++)
#pragma unroll
            for (int q = 0; q < 4; q++) acc[mt][nt][q] = 0.0f;

    float4 breg[8];

    auto ldg_b = [&](int c) {
#pragma unroll
        for (int i = 0; i < 8; i++) {
            int t = tid + i * GEMM_T;          // 0..2047 float4 slots
            int row = t >> 5, q = t & 31;
            int vr = v0 + row;
            float4 b = make_float4(0.f, 0.f, 0.f, 0.f);
            if (vr < VOCAB) b = *(const float4*)(B + (size_t)vr * HDIM + c * KC + q * 4);
            breg[i] = b;
        }
    };
    auto cpa_a = [&](int c, int s) {
        uint32_t dstA = sbase + s * STAGE_BYTES;
#pragma unroll
        for (int i = 0; i < 16; i++) {
            int t = tid + i * GEMM_T;          // 0..4095 cp16 slots
            int arr = t >> 11;                 // 0=hi 1=lo
            int idx = t & 2047;
            int row = idx >> 4, seg = idx & 15;
            const __nv_bfloat16* src = (arr ? g_Al : g_Ah) + row * HDIM + c * KC + seg * 8;
            cp16(dstA + arr * A_BYTES + row * (SPITCH * 2) + seg * 16, src);
        }
        asm volatile("cp.async.commit_group;" ::: "memory");
    };
    auto sts_b = [&](int s) {
        char* bh = sm + s * STAGE_BYTES + 2 * A_BYTES;
        char* bl = bh + B_BYTES;
#pragma unroll
        for (int i = 0; i < 8; i++) {
            int t = tid + i * GEMM_T;
            int row = t >> 5, q = t & 31;
            float4 b = breg[i];
            __nv_bfloat162 h01 = __floats2bfloat162_rn(b.x, b.y);
            __nv_bfloat162 h23 = __floats2bfloat162_rn(b.z, b.w);
            float r0 = b.x - __bfloat162float(h01.x);
            float r1 = b.y - __bfloat162float(h01.y);
            float r2 = b.z - __bfloat162float(h23.x);
            float r3 = b.w - __bfloat162float(h23.y);
            __nv_bfloat162 l01 = __floats2bfloat162_rn(r0, r1);
            __nv_bfloat162 l23 = __floats2bfloat162_rn(r2, r3);
            int off = row * (SPITCH * 2) + q * 8;
            *(uint2*)(bh + off) = make_uint2(*(uint32_t*)&h01, *(uint32_t*)&h23);
            *(uint2*)(bl + off) = make_uint2(*(uint32_t*)&l01, *(uint32_t*)&l23);
        }
    };

    // ---- preload chunk 0 ----
    ldg_b(0);
    cpa_a(0, 0);
    sts_b(0);
    asm volatile("cp.async.wait_group 0;" ::: "memory");
    __syncthreads();

    for (int c = 0; c < NCHUNK; ++c) {
        const int s = c & 1;
        if (c + 1 < NCHUNK) {
            ldg_b(c + 1);
            cpa_a(c + 1, s ^ 1);
        }

        const uint32_t stAh = sbase + s * STAGE_BYTES;
        const uint32_t stAl = stAh + A_BYTES;
        const uint32_t stBh = stAh + 2 * A_BYTES;
        const uint32_t stBl = stBh + B_BYTES;
        const int m0 = wm * 32;
        const int n0 = wn * 32;
#pragma unroll
        for (int ks = 0; ks < 8; ks++) {
            const int kk = ks * 16;
            uint32_t ah[2][4], al[2][4], bh[2][4], bl[2][4];
#pragma unroll
            for (int mt = 0; mt < 2; mt++) {
                int e = (m0 + mt * 16) * SPITCH + kk + a_off;
                ldsm_x4(ah[mt], stAh + e * 2);
                ldsm_x4(al[mt], stAl + e * 2);
            }
#pragma unroll
            for (int ntp = 0; ntp < 2; ntp++) {
                int e = (n0 + ntp * 16) * SPITCH + kk + b_off;
                ldsm_x4(bh[ntp], stBh + e * 2);
                ldsm_x4(bl[ntp], stBl + e * 2);
            }
#pragma unroll
            for (int mt = 0; mt < 2; mt++)
#pragma unroll
                for (int nt = 0; nt < 4; nt++) {
                    int ntp = nt >> 1, j = nt & 1;
                    uint32_t b0h = bh[ntp][j * 2], b1h = bh[ntp][j * 2 + 1];
                    uint32_t b0l = bl[ntp][j * 2], b1l = bl[ntp][j * 2 + 1];
                    mma_bf16(acc[mt][nt], ah[mt], b0h, b1h);
                    mma_bf16(acc[mt][nt], al[mt], b0h, b1h);
                    mma_bf16(acc[mt][nt], ah[mt], b0l, b1l);
                }
        }

        if (c + 1 < NCHUNK) {
            sts_b(s ^ 1);                      // s^1 reads finished at prev barrier
            asm volatile("cp.async.wait_group 0;" ::: "memory");
        }
        __syncthreads();
    }

    // ---- epilogue: scalar stores (VOCAB odd -> float2 misaligns on odd rows) ----
    const int g = l >> 2, t4 = l & 3;
#pragma unroll
    for (int mt = 0; mt < 2; mt++) {
        int row = wm * 32 + mt * 16 + g;
#pragma unroll
        for (int nt = 0; nt < 4; nt++) {
            int col = v0 + wn * 32 + nt * 8 + t4 * 2;
            if (col < VOCAB) {
                float* p0 = C + (size_t)row * VOCAB + col;
                float* p1 = C + (size_t)(row + 8) * VOCAB + col;
                p0[0] = acc[mt][nt][0];
                p1[0] = acc[mt][nt][2];
                if (col + 1 < VOCAB) {
                    p0[1] = acc[mt][nt][1];
                    p1[1] = acc[mt][nt][3];
                }
            }
        }
    }
}

// ==================== Fused penalties + top-p/top-k + softmax (R14 verbatim) ====================
#define TPB 512
#define CAP 2048

__device__ __forceinline__ unsigned fmap(float x) {
    unsigned u = __float_as_uint(x);
    return (u & 0x80000000u) ? ~u : (u | 0x80000000u);
}
__device__ __forceinline__ float warpMax(float v) {
#pragma unroll
    for (int o = 16; o; o >>= 1) v = fmaxf(v, __shfl_xor_sync(0xFFFFFFFFu, v, o));
    return v;
}
__device__ __forceinline__ float warpSum(float v) {
#pragma unroll
    for (int o = 16; o; o >>= 1) v += __shfl_xor_sync(0xFFFFFFFFu, v, o);
    return v;
}
__device__ float blockMax(float v, float* sh) {
    v = warpMax(v);
    int w = threadIdx.x >> 5, l = threadIdx.x & 31;
    if (l == 0) sh[w] = v;
    __syncthreads();
    if (w == 0) {
        float x = (l < (TPB >> 5)) ? sh[l] : -INFINITY;
        x = warpMax(x);
        if (l == 0) sh[0] = x;
    }
    __syncthreads();
    float r = sh[0];
    __syncthreads();
    return r;
}
__device__ float blockSum(float v, float* sh) {
    v = warpSum(v);
    int w = threadIdx.x >> 5, l = threadIdx.x & 31;
    if (l == 0) sh[w] = v;
    __syncthreads();
    if (w == 0) {
        float x = (l < (TPB >> 5)) ? sh[l] : 0.0f;
        x = warpSum(x);
        if (l == 0) sh[0] = x;
    }
    __syncthreads();
    float r = sh[0];
    __syncthreads();
    return r;
}

template <int S>
__device__ void sort_scan(float* cand, int* cidx, float* ps,
                          int ncand, int topk, float topp, float m1, float invZ,
                          int* m_sh, int* j_sh)
{
    const int tid = threadIdx.x;
    for (int i = tid; i < S; i += TPB)
        if (i >= ncand) cand[i] = -INFINITY;
    __syncthreads();

    for (int size = 2; size <= S; size <<= 1) {
        for (int stride = size >> 1; stride > 0; stride >>= 1) {
            for (int i = tid; i < S; i += TPB) {
                int j = i ^ stride;
                if (j > i) {
                    float a = cand[i], b = cand[j];
                    bool desc = ((i & size) == 0);
                    if (desc ? (a < b) : (a > b)) {
                        cand[i] = b; cand[j] = a;
                        int ta = cidx[i]; cidx[i] = cidx[j]; cidx[j] = ta;
                    }
                }
            }
            __syncthreads();
        }
    }

    for (int i = tid; i < S; i += TPB) ps[i] = __expf(cand[i] - m1) * invZ;
    __syncthreads();
    for (int off = 1; off < S; off <<= 1) {
        float t0[S / TPB];
#pragma unroll
        for (int q = 0; q < S / TPB; q++) {
            int i = tid + q * TPB;
            t0[q] = (i >= off) ? ps[i - off] : 0.0f;
        }
        __syncthreads();
#pragma unroll
        for (int q = 0; q < S / TPB; q++) ps[tid + q * TPB] += t0[q];
        __syncthreads();
    }

    if (tid == 0) *m_sh = 1;
    __syncthreads();
    const int limit = min(topk, ncand);
#pragma unroll
    for (int q = 0; q < S / TPB; q++) {
        int i = tid + q * TPB;
        if (i > 0 && i < limit) {
            if (ps[i - 1] <= topp) atomicMax(m_sh, i + 1);
        }
    }
    __syncthreads();
    const float t_x = cand[*m_sh - 1];
    if (tid == 0) *j_sh = *m_sh - 1;
    __syncthreads();
    for (int i = tid; i < ncand; i += TPB)
        if (cand[i] >= t_x) atomicMax(j_sh, i);
    __syncthreads();
}

__global__ __launch_bounds__(TPB) void sample_kernel(
    float* __restrict__ logits,
    const int* __restrict__ out_tokens,
    const float* __restrict__ pres,
    const float* __restrict__ freq,
    const float* __restrict__ rep,
    const float* __restrict__ temps,
    const float* __restrict__ top_ps,
    const int* __restrict__ top_ks)
{
    const int r   = blockIdx.x;
    const int tid = threadIdx.x;
    float* row = logits + (size_t)r * VOCAB;

    __shared__ int toksh[LTOK];
    for (int i = tid; i < LTOK; i += TPB) toksh[i] = out_tokens[r * LTOK + i];
    __syncthreads();
    {
        const float rp = rep[r], fp = freq[r], pp = pres[r];
        for (int i = tid; i < LTOK; i += TPB) {
            int t = toksh[i];
            int cnt = 0;
            bool first = true;
            for (int j = 0; j < LTOK; j++) {
                if (toksh[j] == t) { cnt++; if (j < i) first = false; }
            }
            if (first) {
                float lg = row[t];
                lg = (lg > 0.0f) ? (lg / rp) : (lg * rp);
                row[t] = lg - fp * (float)cnt - pp;
            }
        }
    }
    __syncthreads();

    const float invT = 1.0f / temps[r];
    const float topp = top_ps[r];
    int topk = top_ks[r];
    if (topk < 1) topk = 1;
    if (topk > CAP - 1) topk = CAP - 1;

    __shared__ float sred[32];
    __shared__ unsigned hist[256];
    __shared__ float cand[CAP];
    __shared__ int   cidx[CAP];
    __shared__ float ps[CAP];
    __shared__ int cnt_sh;
    __shared__ unsigned s_T;
    __shared__ int s_SH;
    __shared__ unsigned s_pref;
    __shared__ int s_kk;
    __shared__ int s_g;
    __shared__ int s_need_fb;
    __shared__ int m_sh, j_sh;

    const int head = (4 - (r & 3)) & 3;
    const int nvec = (VOCAB - head) >> 2;
    const float4* vrow = (const float4*)(row + head);
    const int tbase = head + 4 * nvec;
    const int tcnt  = VOCAB - tbase;

    auto forall = [&](auto&& op) {
        if (tid < head) op(row[tid] * invT, tid);
        int i = tid;
        for (; i + 3 * TPB < nvec; i += 4 * TPB) {
            float4 x0 = vrow[i];
            float4 x1 = vrow[i + TPB];
            float4 x2 = vrow[i + 2 * TPB];
            float4 x3 = vrow[i + 3 * TPB];
            int v0i = head + 4 * i;
            int v1i = head + 4 * (i + TPB);
            int v2i = head + 4 * (i + 2 * TPB);
            int v3i = head + 4 * (i + 3 * TPB);
            op(x0.x * invT, v0i); op(x0.y * invT, v0i + 1);
            op(x0.z * invT, v0i + 2); op(x0.w * invT, v0i + 3);
            op(x1.x * invT, v1i); op(x1.y * invT, v1i + 1);
            op(x1.z * invT, v1i + 2); op(x1.w * invT, v1i + 3);
            op(x2.x * invT, v2i); op(x2.y * invT, v2i + 1);
            op(x2.z * invT, v2i + 2); op(x2.w * invT, v2i + 3);
            op(x3.x * invT, v3i); op(x3.y * invT, v3i + 1);
            op(x3.z * invT, v3i + 2); op(x3.w * invT, v3i + 3);
        }
        for (; i < nvec; i += TPB) {
            float4 x4 = vrow[i];
            int v = head + 4 * i;
            op(x4.x * invT, v); op(x4.y * invT, v + 1);
            op(x4.z * invT, v + 2); op(x4.w * invT, v + 3);
        }
        if (tid < tcnt) op(row[tbase + tid] * invT, tbase + tid);
    };

    for (int b = tid; b < 256; b += TPB) hist[b] = 0u;
    __syncthreads();
    float vmax = -INFINITY;
    forall([&](float x, int v) {
        vmax = fmaxf(vmax, x);
        atomicAdd(&hist[fmap(x) >> 24], 1u);
    });
    const float m1 = blockMax(vmax, sred);

    if (tid == 0) {
        int cum = 0, b = 255;
        for (; b >= 0; b--) { cum += (int)hist[b]; if (cum >= topk) break; }
        if (b < 0) b = 0;
        s_g    = cum - (int)hist[b];
        s_kk   = topk - s_g;
        s_pref = (unsigned)b;
    }
    __syncthreads();
    const unsigned b0 = s_pref;
    __syncthreads();

    for (int b = tid; b < 256; b += TPB) hist[b] = 0u;
    __syncthreads();
    float zs = 0.0f;
    forall([&](float x, int v) {
        unsigned u = fmap(x);
        zs += __expf(x - m1);
        if ((u >> 24) == b0) atomicAdd(&hist[(u >> 16) & 0xFFu], 1u);
    });
    const float Z = blockSum(zs, sred);
    const float invZ = 1.0f / Z;

    if (tid == 0) {
        int kk = s_kk, cum = 0, b = 255;
        for (; b >= 0; b--) { cum += (int)hist[b]; if (cum >= kk) break; }
        if (b < 0) b = 0;
        int g1 = cum - (int)hist[b];
        int total_ge = s_g + g1 + (int)hist[b];
        s_g   = s_g + g1;
        s_kk  = kk - g1;
        s_pref = (b0 << 8) | (unsigned)b;
        if (total_ge <= CAP) { s_T = s_pref; s_SH = 16; s_need_fb = 0; }
        else s_need_fb = 1;
    }
    __syncthreads();

    if (s_need_fb) {
        for (int pass = 2; pass < 4; pass++) {
            const int shift = 24 - 8 * pass;
            const unsigned pref = s_pref;
            for (int b = tid; b < 256; b += TPB) hist[b] = 0u;
            __syncthreads();
            forall([&](float x, int v) {
                unsigned u = fmap(x);
                if ((u >> (shift + 8)) == pref) atomicAdd(&hist[(u >> shift) & 0xFFu], 1u);
            });
            __syncthreads();
            if (tid == 0) {
                int kk = s_kk, cum = 0, b = 255;
                for (; b >= 0; b--) { cum += (int)hist[b]; if (cum >= kk) break; }
                if (b < 0) b = 0;
                s_kk = kk - (cum - (int)hist[b]);
                s_pref = (s_pref << 8) | (unsigned)b;
            }
            __syncthreads();
        }
        if (tid == 0) { s_T = s_pref; s_SH = 0; }
        __syncthreads();
    }
    const unsigned T = s_T;
    const int SH = s_SH;

    if (tid == 0) cnt_sh = 0;
    __syncthreads();
    forall([&](float x, int v) {
        if ((fmap(x) >> SH) >= T) {
            int i = atomicAdd(&cnt_sh, 1);
            if (i < CAP) { cand[i] = x; cidx[i] = v; }
        }
    });
    __syncthreads();
    const int ncand = min(cnt_sh, CAP);

    if (ncand <= 1024)
        sort_scan<1024>(cand, cidx, ps, ncand, topk, topp, m1, invZ, &m_sh, &j_sh);
    else
        sort_scan<2048>(cand, cidx, ps, ncand, topk, topp, m1, invZ, &m_sh, &j_sh);

    const int m = m_sh;
    const float t_x = cand[m - 1];
    const float Zk = ps[j_sh] * Z;
    const float invZk = 1.0f / Zk;

    {
        float4 z4 = make_float4(0.f, 0.f, 0.f, 0.f);
        if (tid < head) row[tid] = 0.f;
        float4* wrow = (float4*)(row + head);
        for (int i = tid; i < nvec; i += TPB) wrow[i] = z4;
        if (tid < tcnt) row[tbase + tid] = 0.f;
    }
    __syncthreads();
    for (int i = tid; i < ncand; i += TPB) {
        if (cand[i] >= t_x) row[cidx[i]] = __expf(cand[i] - m1) * invZk;
    }
}

// ==================== launch ====================
extern "C" void kernel_launch(void* const* d_in, const int* in_sizes, int n_in,
                              void* d_out, int out_size)
{
    const float* hidden = (const float*)d_in[0];   // [128,4096]
    const float* emb    = (const float*)d_in[1];   // [50257,4096]
    const int*   toks   = (const int*)  d_in[2];   // [128,200]
    const float* pres   = (const float*)d_in[3];
    const float* freq   = (const float*)d_in[4];
    const float* rep    = (const float*)d_in[5];
    const float* temps  = (const float*)d_in[6];
    const float* topps  = (const float*)d_in[7];
    const int*   topks  = (const int*)  d_in[8];
    float* out = (float*)d_out;                    // [128,50257] probs; logits scratch

    cudaFuncSetAttribute(gemm_hmma, cudaFuncAttributeMaxDynamicSharedMemorySize, SMEM_DYN);

    convert_a_kernel<<<(NROWS * HDIM / 4 + 255) / 256, 256>>>(hidden);
    gemm_hmma<<<(VOCAB + NTILE - 1) / NTILE, GEMM_T, SMEM_DYN>>>(emb, out);
    sample_kernel<<<NROWS, TPB>>>(out, toks, pres, freq, rep, temps, topps, topks);
}

// round 17
// speedup vs baseline: 1.1935x; 1.1935x over previous
#include <cuda_runtime.h>
#include <cuda_bf16.h>
#include <math.h>
#include <stdint.h>

#define NROWS 128
#define VOCAB 50257
#define HDIM  4096
#define LTOK  200

// ==================== A pre-split (fp32 -> bf16 hi + bf16 lo) ====================

__device__ __nv_bfloat16 g_Ah[NROWS * HDIM];
__device__ __nv_bfloat16 g_Al[NROWS * HDIM];

__global__ void convert_a_kernel(const float* __restrict__ A) {
    int i = (blockIdx.x * blockDim.x + threadIdx.x) * 4;
    if (i >= NROWS * HDIM) return;
    float4 a = *(const float4*)(A + i);
    __nv_bfloat162 h01 = __floats2bfloat162_rn(a.x, a.y);
    __nv_bfloat162 h23 = __floats2bfloat162_rn(a.z, a.w);
    float r0 = a.x - __bfloat162float(h01.x);
    float r1 = a.y - __bfloat162float(h01.y);
    float r2 = a.z - __bfloat162float(h23.x);
    float r3 = a.w - __bfloat162float(h23.y);
    __nv_bfloat162 l01 = __floats2bfloat162_rn(r0, r1);
    __nv_bfloat162 l23 = __floats2bfloat162_rn(r2, r3);
    *(uint2*)(g_Ah + i) = make_uint2(*(uint32_t*)&h01, *(uint32_t*)&h23);
    *(uint2*)(g_Al + i) = make_uint2(*(uint32_t*)&l01, *(uint32_t*)&l23);
}

// ==================== HMMA GEMM: C[128,V] = A[128,H] * B[V,H]^T ====================
// Proven optimum: KC=64, M128xN64 CTA, 256 threads, 2 CTAs/SM, 3 split-bf16 terms.

#define KC 64
#define NCHUNK (HDIM / KC)
#define SPITCH 72
#define A_BYTES (128 * SPITCH * 2)
#define B_BYTES (64 * SPITCH * 2)
#define STAGE_BYTES (2 * A_BYTES + 2 * B_BYTES)
#define GEMM_T 256
#define NTILE 64
#define SMEM_DYN (2 * STAGE_BYTES)

__device__ __forceinline__ uint32_t smem_u32(const void* p) {
    uint32_t a;
    asm("{ .reg .u64 t; cvta.to.shared.u64 t, %1; cvt.u32.u64 %0, t; }" : "=r"(a) : "l"(p));
    return a;
}
__device__ __forceinline__ void ldsm_x4(uint32_t* r, uint32_t addr) {
    asm volatile("ldmatrix.sync.aligned.m8n8.x4.shared.b16 {%0,%1,%2,%3}, [%4];"
                 : "=r"(r[0]), "=r"(r[1]), "=r"(r[2]), "=r"(r[3]) : "r"(addr));
}
__device__ __forceinline__ void mma_bf16(float* d, const uint32_t* a, uint32_t b0, uint32_t b1) {
    asm volatile("mma.sync.aligned.m16n8k16.row.col.f32.bf16.bf16.f32 "
                 "{%0,%1,%2,%3}, {%4,%5,%6,%7}, {%8,%9}, {%0,%1,%2,%3};"
                 : "+f"(d[0]), "+f"(d[1]), "+f"(d[2]), "+f"(d[3])
                 : "r"(a[0]), "r"(a[1]), "r"(a[2]), "r"(a[3]), "r"(b0), "r"(b1));
}
__device__ __forceinline__ void cp16(uint32_t dst, const void* src) {
    asm volatile("cp.async.cg.shared.global [%0], [%1], 16;" :: "r"(dst), "l"(src) : "memory");
}

extern __shared__ char dynsmem[];

__global__ __launch_bounds__(GEMM_T, 2) void gemm_hmma(
    const float* __restrict__ B, float* __restrict__ C)
{
    char* sm = dynsmem;
    const uint32_t sbase = smem_u32(sm);
    const int tid = threadIdx.x;
    const int l   = tid & 31;
    const int w   = tid >> 5;
    const int wm  = w & 3;
    const int wn  = w >> 2;
    const int v0  = blockIdx.x * NTILE;

    const int a_off = (l & 15) * SPITCH + ((l >> 4) << 3);
    const int b_off = (((l >> 4) << 3) + (l & 7)) * SPITCH + (((l >> 3) & 1) << 3);

    float acc[2][4][4];
#pragma unroll
    for (int mt = 0; mt < 2; mt++)
#pragma unroll
        for (int nt = 0; nt < 4; nt++)
#pragma unroll
            for (int q = 0; q < 4; q++) acc[mt][nt][q] = 0.0f;

    float4 breg[4];

    auto ldg_b = [&](int c) {
#pragma unroll
        for (int i = 0; i < 4; i++) {
            int t = tid + i * GEMM_T;
            int row = t >> 4, q = t & 15;
            int vr = v0 + row;
            float4 b = make_float4(0.f, 0.f, 0.f, 0.f);
            if (vr < VOCAB) b = *(const float4*)(B + (size_t)vr * HDIM + c * KC + q * 4);
            breg[i] = b;
        }
    };
    auto cpa_a = [&](int c, int s) {
        uint32_t dstA = sbase + s * STAGE_BYTES;
#pragma unroll
        for (int i = 0; i < 8; i++) {
            int t = tid + i * GEMM_T;
            int arr = t >> 10;
            int idx = t & 1023;
            int row = idx >> 3, q = idx & 7;
            const __nv_bfloat16* src = (arr ? g_Al : g_Ah) + row * HDIM + c * KC + q * 8;
            cp16(dstA + arr * A_BYTES + row * (SPITCH * 2) + q * 16, src);
        }
        asm volatile("cp.async.commit_group;" ::: "memory");
    };
    auto sts_b = [&](int s) {
        char* bh = sm + s * STAGE_BYTES + 2 * A_BYTES;
        char* bl = bh + B_BYTES;
#pragma unroll
        for (int i = 0; i < 4; i++) {
            int t = tid + i * GEMM_T;
            int row = t >> 4, q = t & 15;
            float4 b = breg[i];
            __nv_bfloat162 h01 = __floats2bfloat162_rn(b.x, b.y);
            __nv_bfloat162 h23 = __floats2bfloat162_rn(b.z, b.w);
            float r0 = b.x - __bfloat162float(h01.x);
            float r1 = b.y - __bfloat162float(h01.y);
            float r2 = b.z - __bfloat162float(h23.x);
            float r3 = b.w - __bfloat162float(h23.y);
            __nv_bfloat162 l01 = __floats2bfloat162_rn(r0, r1);
            __nv_bfloat162 l23 = __floats2bfloat162_rn(r2, r3);
            int off = row * (SPITCH * 2) + q * 8;
            *(uint2*)(bh + off) = make_uint2(*(uint32_t*)&h01, *(uint32_t*)&h23);
            *(uint2*)(bl + off) = make_uint2(*(uint32_t*)&l01, *(uint32_t*)&l23);
        }
    };

    ldg_b(0);
    cpa_a(0, 0);
    sts_b(0);
    asm volatile("cp.async.wait_group 0;" ::: "memory");
    __syncthreads();

    for (int c = 0; c < NCHUNK; ++c) {
        const int s = c & 1;
        if (c + 1 < NCHUNK) {
            ldg_b(c + 1);
            cpa_a(c + 1, s ^ 1);
        }

        const uint32_t stAh = sbase + s * STAGE_BYTES;
        const uint32_t stAl = stAh + A_BYTES;
        const uint32_t stBh = stAh + 2 * A_BYTES;
        const uint32_t stBl = stBh + B_BYTES;
        const int m0 = wm * 32;
        const int n0 = wn * 32;
#pragma unroll
        for (int ks = 0; ks < 4; ks++) {
            const int kk = ks * 16;
            uint32_t ah[2][4], al[2][4], bh[2][4], bl[2][4];
#pragma unroll
            for (int mt = 0; mt < 2; mt++) {
                int e = (m0 + mt * 16) * SPITCH + kk + a_off;
                ldsm_x4(ah[mt], stAh + e * 2);
                ldsm_x4(al[mt], stAl + e * 2);
            }
#pragma unroll
            for (int ntp = 0; ntp < 2; ntp++) {
                int e = (n0 + ntp * 16) * SPITCH + kk + b_off;
                ldsm_x4(bh[ntp], stBh + e * 2);
                ldsm_x4(bl[ntp], stBl + e * 2);
            }
#pragma unroll
            for (int mt = 0; mt < 2; mt++)
#pragma unroll
                for (int nt = 0; nt < 4; nt++) {
                    int ntp = nt >> 1, j = nt & 1;
                    uint32_t b0h = bh[ntp][j * 2], b1h = bh[ntp][j * 2 + 1];
                    uint32_t b0l = bl[ntp][j * 2], b1l = bl[ntp][j * 2 + 1];
                    mma_bf16(acc[mt][nt], ah[mt], b0h, b1h);
                    mma_bf16(acc[mt][nt], al[mt], b0h, b1h);
                    mma_bf16(acc[mt][nt], ah[mt], b0l, b1l);
                }
        }

        if (c + 1 < NCHUNK) {
            sts_b(s ^ 1);
            asm volatile("cp.async.wait_group 0;" ::: "memory");
        }
        __syncthreads();
    }

    const int g = l >> 2, t4 = l & 3;
#pragma unroll
    for (int mt = 0; mt < 2; mt++) {
        int row = wm * 32 + mt * 16 + g;
#pragma unroll
        for (int nt = 0; nt < 4; nt++) {
            int col = v0 + wn * 32 + nt * 8 + t4 * 2;
            if (col < VOCAB) {
                float* p0 = C + (size_t)row * VOCAB + col;
                float* p1 = C + (size_t)(row + 8) * VOCAB + col;
                p0[0] = acc[mt][nt][0];
                p1[0] = acc[mt][nt][2];
                if (col + 1 < VOCAB) {
                    p0[1] = acc[mt][nt][1];
                    p1[1] = acc[mt][nt][3];
                }
            }
        }
    }
}

// ==================== Fused penalties + top-p/top-k + softmax ====================
#define TPB 512
#define CAP 2048

__device__ __forceinline__ unsigned fmap(float x) {
    unsigned u = __float_as_uint(x);
    return (u & 0x80000000u) ? ~u : (u | 0x80000000u);
}
__device__ __forceinline__ float warpMax(float v) {
#pragma unroll
    for (int o = 16; o; o >>= 1) v = fmaxf(v, __shfl_xor_sync(0xFFFFFFFFu, v, o));
    return v;
}
__device__ __forceinline__ float warpSum(float v) {
#pragma unroll
    for (int o = 16; o; o >>= 1) v += __shfl_xor_sync(0xFFFFFFFFu, v, o);
    return v;
}
__device__ float blockMax(float v, float* sh) {
    v = warpMax(v);
    int w = threadIdx.x >> 5, l = threadIdx.x & 31;
    if (l == 0) sh[w] = v;
    __syncthreads();
    if (w == 0) {
        float x = (l < (TPB >> 5)) ? sh[l] : -INFINITY;
        x = warpMax(x);
        if (l == 0) sh[0] = x;
    }
    __syncthreads();
    float r = sh[0];
    __syncthreads();
    return r;
}
__device__ float blockSum(float v, float* sh) {
    v = warpSum(v);
    int w = threadIdx.x >> 5, l = threadIdx.x & 31;
    if (l == 0) sh[w] = v;
    __syncthreads();
    if (w == 0) {
        float x = (l < (TPB >> 5)) ? sh[l] : 0.0f;
        x = warpSum(x);
        if (l == 0) sh[0] = x;
    }
    __syncthreads();
    float r = sh[0];
    __syncthreads();
    return r;
}

template <int S>
__device__ void sort_scan(float* cand, int* cidx, float* ps,
                          int ncand, int topk, float topp, float m1, float invZ,
                          int* m_sh, int* j_sh)
{
    const int tid = threadIdx.x;
    for (int i = tid; i < S; i += TPB)
        if (i >= ncand) cand[i] = -INFINITY;
    __syncthreads();

    for (int size = 2; size <= S; size <<= 1) {
        for (int stride = size >> 1; stride > 0; stride >>= 1) {
            for (int i = tid; i < S; i += TPB) {
                int j = i ^ stride;
                if (j > i) {
                    float a = cand[i], b = cand[j];
                    bool desc = ((i & size) == 0);
                    if (desc ? (a < b) : (a > b)) {
                        cand[i] = b; cand[j] = a;
                        int ta = cidx[i]; cidx[i] = cidx[j]; cidx[j] = ta;
                    }
                }
            }
            __syncthreads();
        }
    }

    for (int i = tid; i < S; i += TPB) ps[i] = __expf(cand[i] - m1) * invZ;
    __syncthreads();
    for (int off = 1; off < S; off <<= 1) {
        float t0[S / TPB];
#pragma unroll
        for (int q = 0; q < S / TPB; q++) {
            int i = tid + q * TPB;
            t0[q] = (i >= off) ? ps[i - off] : 0.0f;
        }
        __syncthreads();
#pragma unroll
        for (int q = 0; q < S / TPB; q++) ps[tid + q * TPB] += t0[q];
        __syncthreads();
    }

    if (tid == 0) *m_sh = 1;
    __syncthreads();
    const int limit = min(topk, ncand);
#pragma unroll
    for (int q = 0; q < S / TPB; q++) {
        int i = tid + q * TPB;
        if (i > 0 && i < limit) {
            if (ps[i - 1] <= topp) atomicMax(m_sh, i + 1);
        }
    }
    __syncthreads();
    const float t_x = cand[*m_sh - 1];
    if (tid == 0) *j_sh = *m_sh - 1;
    __syncthreads();
    for (int i = tid; i < ncand; i += TPB)
        if (cand[i] >= t_x) atomicMax(j_sh, i);
    __syncthreads();
}

__global__ __launch_bounds__(TPB) void sample_kernel(
    float* __restrict__ logits,
    const int* __restrict__ out_tokens,
    const float* __restrict__ pres,
    const float* __restrict__ freq,
    const float* __restrict__ rep,
    const float* __restrict__ temps,
    const float* __restrict__ top_ps,
    const int* __restrict__ top_ks)
{
    const int r   = blockIdx.x;
    const int tid = threadIdx.x;
    float* row = logits + (size_t)r * VOCAB;

    // ---- fused penalties ----
    __shared__ int toksh[LTOK];
    for (int i = tid; i < LTOK; i += TPB) toksh[i] = out_tokens[r * LTOK + i];
    __syncthreads();
    {
        const float rp = rep[r], fp = freq[r], pp = pres[r];
        for (int i = tid; i < LTOK; i += TPB) {
            int t = toksh[i];
            int cnt = 0;
            bool first = true;
            for (int j = 0; j < LTOK; j++) {
                if (toksh[j] == t) { cnt++; if (j < i) first = false; }
            }
            if (first) {
                float lg = row[t];
                lg = (lg > 0.0f) ? (lg / rp) : (lg * rp);
                row[t] = lg - fp * (float)cnt - pp;
            }
        }
    }
    __syncthreads();

    const float invT = 1.0f / temps[r];
    const float topp = top_ps[r];
    int topk = top_ks[r];
    if (topk < 1) topk = 1;
    if (topk > CAP - 1) topk = CAP - 1;

    __shared__ float sred[32];
    __shared__ unsigned hist[256];
    __shared__ float cand[CAP];
    __shared__ int   cidx[CAP];
    __shared__ float ps[CAP];
    __shared__ int cnt_sh;
    __shared__ unsigned s_T;
    __shared__ int s_SH;
    __shared__ unsigned s_pref;
    __shared__ int s_kk;
    __shared__ int s_g;
    __shared__ int s_need_fb;
    __shared__ int m_sh, j_sh;

    const int head = (4 - (r & 3)) & 3;
    const int nvec = (VOCAB - head) >> 2;
    const float4* vrow = (const float4*)(row + head);
    const int tbase = head + 4 * nvec;
    const int tcnt  = VOCAB - tbase;

    // Batched traversal: 4 independent float4 loads in flight per iteration.
    auto forall = [&](auto&& op) {
        if (tid < head) op(row[tid] * invT, tid);
        int i = tid;
        for (; i + 3 * TPB < nvec; i += 4 * TPB) {
            float4 x0 = vrow[i];
            float4 x1 = vrow[i + TPB];
            float4 x2 = vrow[i + 2 * TPB];
            float4 x3 = vrow[i + 3 * TPB];
            int v0i = head + 4 * i;
            int v1i = head + 4 * (i + TPB);
            int v2i = head + 4 * (i + 2 * TPB);
            int v3i = head + 4 * (i + 3 * TPB);
            op(x0.x * invT, v0i); op(x0.y * invT, v0i + 1);
            op(x0.z * invT, v0i + 2); op(x0.w * invT, v0i + 3);
            op(x1.x * invT, v1i); op(x1.y * invT, v1i + 1);
            op(x1.z * invT, v1i + 2); op(x1.w * invT, v1i + 3);
            op(x2.x * invT, v2i); op(x2.y * invT, v2i + 1);
            op(x2.z * invT, v2i + 2); op(x2.w * invT, v2i + 3);
            op(x3.x * invT, v3i); op(x3.y * invT, v3i + 1);
            op(x3.z * invT, v3i + 2); op(x3.w * invT, v3i + 3);
        }
        for (; i < nvec; i += TPB) {
            float4 x4 = vrow[i];
            int v = head + 4 * i;
            op(x4.x * invT, v); op(x4.y * invT, v + 1);
            op(x4.z * invT, v + 2); op(x4.w * invT, v + 3);
        }
        if (tid < tcnt) op(row[tbase + tid] * invT, tbase + tid);
    };

    // ---- Pass A: max + hist0 ----
    for (int b = tid; b < 256; b += TPB) hist[b] = 0u;
    __syncthreads();
    float vmax = -INFINITY;
    forall([&](float x, int v) {
        vmax = fmaxf(vmax, x);
        atomicAdd(&hist[fmap(x) >> 24], 1u);
    });
    const float m1 = blockMax(vmax, sred);

    if (tid == 0) {
        int cum = 0, b = 255;
        for (; b >= 0; b--) { cum += (int)hist[b]; if (cum >= topk) break; }
        if (b < 0) b = 0;
        s_g    = cum - (int)hist[b];
        s_kk   = topk - s_g;
        s_pref = (unsigned)b;
    }
    __syncthreads();
    const unsigned b0 = s_pref;
    __syncthreads();

    // ---- Pass B: Z + hist1 ----
    for (int b = tid; b < 256; b += TPB) hist[b] = 0u;
    __syncthreads();
    float zs = 0.0f;
    forall([&](float x, int v) {
        unsigned u = fmap(x);
        zs += __expf(x - m1);
        if ((u >> 24) == b0) atomicAdd(&hist[(u >> 16) & 0xFFu], 1u);
    });
    const float Z = blockSum(zs, sred);
    const float invZ = 1.0f / Z;

    if (tid == 0) {
        int kk = s_kk, cum = 0, b = 255;
        for (; b >= 0; b--) { cum += (int)hist[b]; if (cum >= kk) break; }
        if (b < 0) b = 0;
        int g1 = cum - (int)hist[b];
        int total_ge = s_g + g1 + (int)hist[b];
        s_g   = s_g + g1;
        s_kk  = kk - g1;
        s_pref = (b0 << 8) | (unsigned)b;
        if (total_ge <= CAP) { s_T = s_pref; s_SH = 16; s_need_fb = 0; }
        else s_need_fb = 1;
    }
    __syncthreads();

    if (s_need_fb) {
        for (int pass = 2; pass < 4; pass++) {
            const int shift = 24 - 8 * pass;
            const unsigned pref = s_pref;
            for (int b = tid; b < 256; b += TPB) hist[b] = 0u;
            __syncthreads();
            forall([&](float x, int v) {
                unsigned u = fmap(x);
                if ((u >> (shift + 8)) == pref) atomicAdd(&hist[(u >> shift) & 0xFFu], 1u);
            });
            __syncthreads();
            if (tid == 0) {
                int kk = s_kk, cum = 0, b = 255;
                for (; b >= 0; b--) { cum += (int)hist[b]; if (cum >= kk) break; }
                if (b < 0) b = 0;
                s_kk = kk - (cum - (int)hist[b]);
                s_pref = (s_pref << 8) | (unsigned)b;
            }
            __syncthreads();
        }
        if (tid == 0) { s_T = s_pref; s_SH = 0; }
        __syncthreads();
    }
    const unsigned T = s_T;
    const int SH = s_SH;

    // ---- Gather (value,index) ----
    if (tid == 0) cnt_sh = 0;
    __syncthreads();
    forall([&](float x, int v) {
        if ((fmap(x) >> SH) >= T) {
            int i = atomicAdd(&cnt_sh, 1);
            if (i < CAP) { cand[i] = x; cidx[i] = v; }
        }
    });
    __syncthreads();
    const int ncand = min(cnt_sh, CAP);

    // ---- Sort/scan at adaptive size ----
    if (ncand <= 1024)
        sort_scan<1024>(cand, cidx, ps, ncand, topk, topp, m1, invZ, &m_sh, &j_sh);
    else
        sort_scan<2048>(cand, cidx, ps, ncand, topk, topp, m1, invZ, &m_sh, &j_sh);

    const int m = m_sh;
    const float t_x = cand[m - 1];
    const float Zk = ps[j_sh] * Z;
    const float invZk = 1.0f / Zk;

    // ---- zero-fill + sparse scatter ----
    {
        float4 z4 = make_float4(0.f, 0.f, 0.f, 0.f);
        if (tid < head) row[tid] = 0.f;
        float4* wrow = (float4*)(row + head);
        for (int i = tid; i < nvec; i += TPB) wrow[i] = z4;
        if (tid < tcnt) row[tbase + tid] = 0.f;
    }
    __syncthreads();
    for (int i = tid; i < ncand; i += TPB) {
        if (cand[i] >= t_x) row[cidx[i]] = __expf(cand[i] - m1) * invZk;
    }
}

// ==================== launch ====================
extern "C" void kernel_launch(void* const* d_in, const int* in_sizes, int n_in,
                              void* d_out, int out_size)
{
    const float* hidden = (const float*)d_in[0];   // [128,4096]
    const float* emb    = (const float*)d_in[1];   // [50257,4096]
    const int*   toks   = (const int*)  d_in[2];   // [128,200]
    const float* pres   = (const float*)d_in[3];
    const float* freq   = (const float*)d_in[4];
    const float* rep    = (const float*)d_in[5];
    const float* temps  = (const float*)d_in[6];
    const float* topps  = (const float*)d_in[7];
    const int*   topks  = (const int*)  d_in[8];
    float* out = (float*)d_out;                    // [128,50257] probs; logits scratch

    cudaFuncSetAttribute(gemm_hmma, cudaFuncAttributeMaxDynamicSharedMemorySize, SMEM_DYN);

    convert_a_kernel<<<(NROWS * HDIM / 4 + 255) / 256, 256>>>(hidden);
    gemm_hmma<<<(VOCAB + NTILE - 1) / NTILE, GEMM_T, SMEM_DYN>>>(emb, out);
    sample_kernel<<<NROWS, TPB>>>(out, toks, pres, freq, rep, temps, topps, topks);
}